// round 9
// baseline (speedup 1.0000x reference)
#include <cuda_runtime.h>
#include <cstddef>

// Problem constants (fixed by the reference: N=1024, D=16, E=16384)
#define NNODES 1024
#define D_DIM  16
#define NM     16384          // N * D

// Inline edge_index dtype probe (deterministic single word):
// int32 layout (2,32768): word 32769 = edge_index[1][1] = col[1] >= 1 (r < c).
// int64 LE layout: word 32769 = high half of edge_index[0][16384] < 1024 -> 0.
__device__ __forceinline__ int idx_stride(const int* eidx32) {
    return (__ldg(&eidx32[32769]) != 0) ? 1 : 2;
}

// Fused pass (after the memset): 4 edges per CTA, 64 threads per edge.
// A and B are staged TRANSPOSED in smem (contiguous in the contraction index
// i), so the inner product loop runs on LDS.128: 32 vector loads per thread
// instead of 128 scalar loads -> 4x fewer L1tex wavefronts (the measured
// bottleneck at 78.6% L1 utilization).
//   - stages -dr*dc*(A^T B) in smem, float4-coalesced direct stores of the
//     triu block (r,c) and its transpose (c,r) into `out`
//   - atomically accumulates dinv^2-scaled A^T A / B^T B into out's diagonal
//     blocks (memset provides the zero initial value)
__global__ void __launch_bounds__(256) edge_fused_kernel(
        const float* __restrict__ degrees,
        const float* __restrict__ maps,
        const int*   __restrict__ eidx32,
        float*       __restrict__ out,
        int E) {
    __shared__ float At[4][16][20];    // At[g][k][i] = A[i][k], padded rows (80B)
    __shared__ float Bt[4][16][20];
    __shared__ float Tsm[4][16][17];   // scaled T, padded against bank conflicts

    const int tid = threadIdx.x;
    const int g   = tid >> 6;          // edge slot 0..3
    const int lt  = tid & 63;
    const int e   = blockIdx.x * 4 + g;

    const int stride = idx_stride(eidx32);
    const int r = eidx32[(size_t)e * stride];
    const int c = eidx32[(size_t)(2 * E + e) * stride];

    // Stage transposed: thread (row, q) loads one float4 of each map row and
    // scatters it into the transposed tiles.
    {
        const int row = lt >> 2;       // 0..15
        const int q   = lt & 3;        // float4 group 0..3
        const float4 av = *(const float4*)(maps + (size_t)e * 256 + row * 16 + q * 4);
        At[g][q * 4 + 0][row] = av.x;
        At[g][q * 4 + 1][row] = av.y;
        At[g][q * 4 + 2][row] = av.z;
        At[g][q * 4 + 3][row] = av.w;
        const float4 bv = *(const float4*)(maps + ((size_t)e + E) * 256 + row * 16 + q * 4);
        Bt[g][q * 4 + 0][row] = bv.x;
        Bt[g][q * 4 + 1][row] = bv.y;
        Bt[g][q * 4 + 2][row] = bv.z;
        Bt[g][q * 4 + 3][row] = bv.w;
    }
    __syncthreads();

    const int j0 = lt >> 3;            // 0..7   (rows j0, j0+8)
    const int k0 = lt & 7;             // 0..7   (cols k0, k0+8)

    float t00 = 0.f, t01 = 0.f, t10 = 0.f, t11 = 0.f;
    float p00 = 0.f, p01 = 0.f, p10 = 0.f, p11 = 0.f;   // A^T A
    float q00 = 0.f, q01 = 0.f, q10 = 0.f, q11 = 0.f;   // B^T B

    #pragma unroll
    for (int i4 = 0; i4 < 4; ++i4) {
        const float4 aj0 = *(const float4*)&At[g][j0    ][i4 * 4];
        const float4 aj1 = *(const float4*)&At[g][j0 + 8][i4 * 4];
        const float4 ak0 = *(const float4*)&At[g][k0    ][i4 * 4];
        const float4 ak1 = *(const float4*)&At[g][k0 + 8][i4 * 4];
        const float4 bj0 = *(const float4*)&Bt[g][j0    ][i4 * 4];
        const float4 bj1 = *(const float4*)&Bt[g][j0 + 8][i4 * 4];
        const float4 bk0 = *(const float4*)&Bt[g][k0    ][i4 * 4];
        const float4 bk1 = *(const float4*)&Bt[g][k0 + 8][i4 * 4];

        t00 += aj0.x*bk0.x + aj0.y*bk0.y + aj0.z*bk0.z + aj0.w*bk0.w;
        t01 += aj0.x*bk1.x + aj0.y*bk1.y + aj0.z*bk1.z + aj0.w*bk1.w;
        t10 += aj1.x*bk0.x + aj1.y*bk0.y + aj1.z*bk0.z + aj1.w*bk0.w;
        t11 += aj1.x*bk1.x + aj1.y*bk1.y + aj1.z*bk1.z + aj1.w*bk1.w;

        p00 += aj0.x*ak0.x + aj0.y*ak0.y + aj0.z*ak0.z + aj0.w*ak0.w;
        p01 += aj0.x*ak1.x + aj0.y*ak1.y + aj0.z*ak1.z + aj0.w*ak1.w;
        p10 += aj1.x*ak0.x + aj1.y*ak0.y + aj1.z*ak0.z + aj1.w*ak0.w;
        p11 += aj1.x*ak1.x + aj1.y*ak1.y + aj1.z*ak1.z + aj1.w*ak1.w;

        q00 += bj0.x*bk0.x + bj0.y*bk0.y + bj0.z*bk0.z + bj0.w*bk0.w;
        q01 += bj0.x*bk1.x + bj0.y*bk1.y + bj0.z*bk1.z + bj0.w*bk1.w;
        q10 += bj1.x*bk0.x + bj1.y*bk0.y + bj1.z*bk0.z + bj1.w*bk0.w;
        q11 += bj1.x*bk1.x + bj1.y*bk1.y + bj1.z*bk1.z + bj1.w*bk1.w;
    }

    const float dr = rsqrtf(degrees[r] * (float)D_DIM + 1.0f);
    const float dc = rsqrtf(degrees[c] * (float)D_DIM + 1.0f);
    const float s  = -(dr * dc);
    const float sr = dr * dr;
    const float sc = dc * dc;

    // Diagonal Gram contributions straight into out's diag blocks
    float* dgr = &out[(size_t)(r * 16) * NM + r * 16];   // block (r,r), row stride NM
    atomicAdd(&dgr[(size_t)j0 * NM + k0],            sr * p00);
    atomicAdd(&dgr[(size_t)j0 * NM + k0 + 8],        sr * p01);
    atomicAdd(&dgr[(size_t)(j0 + 8) * NM + k0],      sr * p10);
    atomicAdd(&dgr[(size_t)(j0 + 8) * NM + k0 + 8],  sr * p11);

    float* dgc = &out[(size_t)(c * 16) * NM + c * 16];   // block (c,c)
    atomicAdd(&dgc[(size_t)j0 * NM + k0],            sc * q00);
    atomicAdd(&dgc[(size_t)j0 * NM + k0 + 8],        sc * q01);
    atomicAdd(&dgc[(size_t)(j0 + 8) * NM + k0],      sc * q10);
    atomicAdd(&dgc[(size_t)(j0 + 8) * NM + k0 + 8],  sc * q11);

    // Stage the scaled triu block in smem
    Tsm[g][j0][k0]          = s * t00;
    Tsm[g][j0][k0 + 8]      = s * t01;
    Tsm[g][j0 + 8][k0]      = s * t10;
    Tsm[g][j0 + 8][k0 + 8]  = s * t11;
    __syncthreads();

    // Re-map 64 threads to 16 rows x 4 float4 groups for coalesced stores
    const int j = lt >> 2;     // row 0..15
    const int q = lt & 3;      // float4 column group 0..3

    float4 v;                  // triu block, row j
    v.x = Tsm[g][j][q * 4 + 0];
    v.y = Tsm[g][j][q * 4 + 1];
    v.z = Tsm[g][j][q * 4 + 2];
    v.w = Tsm[g][j][q * 4 + 3];
    *(float4*)&out[(size_t)(r * 16 + j) * NM + c * 16 + q * 4] = v;

    float4 w;                  // tril block = transpose, row j
    w.x = Tsm[g][q * 4 + 0][j];
    w.y = Tsm[g][q * 4 + 1][j];
    w.z = Tsm[g][q * 4 + 2][j];
    w.w = Tsm[g][q * 4 + 3][j];
    *(float4*)&out[(size_t)(c * 16 + j) * NM + r * 16 + q * 4] = w;
}

extern "C" void kernel_launch(void* const* d_in, const int* in_sizes, int n_in,
                              void* d_out, int out_size) {
    // Inputs (metadata order): adj_mat [N*N f32], degrees [N f32],
    // maps [2E*16*16 f32], edge_index [2*2E int]
    const float* degrees = (const float*)d_in[1];
    const float* maps    = (const float*)d_in[2];
    const int*   eidx32  = (const int*)d_in[3];
    float*       out     = (float*)d_out;

    const int E = in_sizes[2] / (2 * 256);   // maps has 2E blocks of 256 floats

    // 1) Pure bandwidth-optimal zero fill of the 1.07 GB output (serial:
    //    measured ~7.2 TB/s; any overlap degrades it — R5/R6 evidence)
    cudaMemsetAsync(d_out, 0, (size_t)out_size * sizeof(float), 0);

    // 2) Fused: compute + direct triu/tril stores + diag atomics into out
    edge_fused_kernel<<<E / 4, 256>>>(degrees, maps, eidx32, out, E);
}